// round 12
// baseline (speedup 1.0000x reference)
#include <cuda_runtime.h>
#include <cuda_bf16.h>
#include <cstdint>

// VDP dropout: keep = (u >= 0.1)
//   mu_out    = mu_in    * keep / 0.9
//   Sigma_out = Sigma_in * keep / 768
//
// FINAL — measured-best config across the full experiment matrix:
//   R1/R11 (this config)              : 24.26-24.58us ncu  <= best
//   R3  VPT=4 front-batch + .cs both  : 25.86us (cross-CTA L1tex spread)
//   R4  .cs stores                    : 24.58us (neutral)
//   R6  persistent grid-stride        : 26.30us (fewer outstanding loads)
//   R10 512-thread blocks             : 25.54us (coarser sched granule)
// One float4 per thread, 256-thread blocks, one-shot grid (9457 CTAs),
// default cache policy. 193.7MB irreducible traffic (3R+2W, no reuse) at
// ~8.0 TB/s effective = ~100% of the HBM3e spec: streaming roofline.

static constexpr float DROP_PROP = 0.1f;
static constexpr float INV_KEEP  = 1.0f / (1.0f - DROP_PROP);   // 1/0.9
static constexpr float INV_D     = 1.0f / 768.0f;

__global__ void __launch_bounds__(256)
vdp_dropout_kernel(const float4* __restrict__ mu,
                   const float4* __restrict__ sigma,
                   const float4* __restrict__ u,
                   float4* __restrict__ mu_out,
                   float4* __restrict__ sigma_out,
                   int n4)
{
    int i = blockIdx.x * blockDim.x + threadIdx.x;
    if (i >= n4) return;

    float4 m = mu[i];
    float4 s = sigma[i];
    float4 r = u[i];

    float4 mo, so;
    mo.x = (r.x >= DROP_PROP) ? m.x * INV_KEEP : 0.0f;
    mo.y = (r.y >= DROP_PROP) ? m.y * INV_KEEP : 0.0f;
    mo.z = (r.z >= DROP_PROP) ? m.z * INV_KEEP : 0.0f;
    mo.w = (r.w >= DROP_PROP) ? m.w * INV_KEEP : 0.0f;
    so.x = (r.x >= DROP_PROP) ? s.x * INV_D : 0.0f;
    so.y = (r.y >= DROP_PROP) ? s.y * INV_D : 0.0f;
    so.z = (r.z >= DROP_PROP) ? s.z * INV_D : 0.0f;
    so.w = (r.w >= DROP_PROP) ? s.w * INV_D : 0.0f;

    mu_out[i]    = mo;
    sigma_out[i] = so;
}

extern "C" void kernel_launch(void* const* d_in, const int* in_sizes, int n_in,
                              void* d_out, int out_size)
{
    const float* mu    = (const float*)d_in[0];
    const float* sigma = (const float*)d_in[1];
    const float* u     = (const float*)d_in[2];
    float* out = (float*)d_out;

    int n = in_sizes[0];            // 9,683,456 elements
    int n4 = n / 4;                 // 2,420,864 float4s

    float* mu_out    = out;         // outputs concatenated: (mu_out, Sigma_out)
    float* sigma_out = out + n;

    int threads = 256;
    int blocks = (n4 + threads - 1) / threads;   // 9457
    vdp_dropout_kernel<<<blocks, threads>>>(
        (const float4*)mu, (const float4*)sigma, (const float4*)u,
        (float4*)mu_out, (float4*)sigma_out, n4);
}

// round 13
// speedup vs baseline: 1.0076x; 1.0076x over previous
#include <cuda_runtime.h>
#include <cuda_bf16.h>
#include <cstdint>

// VDP dropout: keep = (u >= 0.1)
//   mu_out    = mu_in    * keep / 0.9
//   Sigma_out = Sigma_in * keep / 768
//
// FINAL — measured-best config across the full experiment matrix:
//   R1/R11/R12 (this config)          : 24.26-24.74us ncu  <= best
//   R3  VPT=4 front-batch + .cs both  : 25.86us (cross-CTA L1tex spread)
//   R4  .cs stores                    : 24.58us (neutral)
//   R6  persistent grid-stride        : 26.30us (fewer outstanding loads)
//   R10 512-thread blocks             : 25.54us (coarser sched granule)
// One float4 per thread, 256-thread blocks, one-shot grid (9457 CTAs),
// default cache policy. 193.7MB irreducible traffic (3R+2W, no reuse) at
// ~8.0 TB/s effective = ~100% of the HBM3e spec: streaming roofline.

static constexpr float DROP_PROP = 0.1f;
static constexpr float INV_KEEP  = 1.0f / (1.0f - DROP_PROP);   // 1/0.9
static constexpr float INV_D     = 1.0f / 768.0f;

__global__ void __launch_bounds__(256)
vdp_dropout_kernel(const float4* __restrict__ mu,
                   const float4* __restrict__ sigma,
                   const float4* __restrict__ u,
                   float4* __restrict__ mu_out,
                   float4* __restrict__ sigma_out,
                   int n4)
{
    int i = blockIdx.x * blockDim.x + threadIdx.x;
    if (i >= n4) return;

    float4 m = mu[i];
    float4 s = sigma[i];
    float4 r = u[i];

    float4 mo, so;
    mo.x = (r.x >= DROP_PROP) ? m.x * INV_KEEP : 0.0f;
    mo.y = (r.y >= DROP_PROP) ? m.y * INV_KEEP : 0.0f;
    mo.z = (r.z >= DROP_PROP) ? m.z * INV_KEEP : 0.0f;
    mo.w = (r.w >= DROP_PROP) ? m.w * INV_KEEP : 0.0f;
    so.x = (r.x >= DROP_PROP) ? s.x * INV_D : 0.0f;
    so.y = (r.y >= DROP_PROP) ? s.y * INV_D : 0.0f;
    so.z = (r.z >= DROP_PROP) ? s.z * INV_D : 0.0f;
    so.w = (r.w >= DROP_PROP) ? s.w * INV_D : 0.0f;

    mu_out[i]    = mo;
    sigma_out[i] = so;
}

extern "C" void kernel_launch(void* const* d_in, const int* in_sizes, int n_in,
                              void* d_out, int out_size)
{
    const float* mu    = (const float*)d_in[0];
    const float* sigma = (const float*)d_in[1];
    const float* u     = (const float*)d_in[2];
    float* out = (float*)d_out;

    int n = in_sizes[0];            // 9,683,456 elements
    int n4 = n / 4;                 // 2,420,864 float4s

    float* mu_out    = out;         // outputs concatenated: (mu_out, Sigma_out)
    float* sigma_out = out + n;

    int threads = 256;
    int blocks = (n4 + threads - 1) / threads;   // 9457
    vdp_dropout_kernel<<<blocks, threads>>>(
        (const float4*)mu, (const float4*)sigma, (const float4*)u,
        (float4*)mu_out, (float4*)sigma_out, n4);
}

// round 14
// speedup vs baseline: 1.0173x; 1.0096x over previous
#include <cuda_runtime.h>
#include <cuda_bf16.h>
#include <cstdint>

// VDP dropout: keep = (u >= 0.1)
//   mu_out    = mu_in    * keep / 0.9
//   Sigma_out = Sigma_in * keep / 768
//
// FINAL — measured-best config across the full experiment matrix:
//   R1/R11/R12/R13 (this config)      : 24.26-24.74us ncu  <= best
//   R3  VPT=4 front-batch + .cs both  : 25.86us (cross-CTA L1tex spread)
//   R4  .cs stores                    : 24.58us (neutral)
//   R6  persistent grid-stride        : 26.30us (fewer outstanding loads)
//   R10 512-thread blocks             : 25.54us (coarser sched granule)
// One float4 per thread, 256-thread blocks, one-shot grid (9457 CTAs),
// default cache policy. 193.7MB irreducible traffic (3R+2W, no reuse) at
// ~8.0 TB/s effective = ~100% of the HBM3e spec: streaming roofline.

static constexpr float DROP_PROP = 0.1f;
static constexpr float INV_KEEP  = 1.0f / (1.0f - DROP_PROP);   // 1/0.9
static constexpr float INV_D     = 1.0f / 768.0f;

__global__ void __launch_bounds__(256)
vdp_dropout_kernel(const float4* __restrict__ mu,
                   const float4* __restrict__ sigma,
                   const float4* __restrict__ u,
                   float4* __restrict__ mu_out,
                   float4* __restrict__ sigma_out,
                   int n4)
{
    int i = blockIdx.x * blockDim.x + threadIdx.x;
    if (i >= n4) return;

    float4 m = mu[i];
    float4 s = sigma[i];
    float4 r = u[i];

    float4 mo, so;
    mo.x = (r.x >= DROP_PROP) ? m.x * INV_KEEP : 0.0f;
    mo.y = (r.y >= DROP_PROP) ? m.y * INV_KEEP : 0.0f;
    mo.z = (r.z >= DROP_PROP) ? m.z * INV_KEEP : 0.0f;
    mo.w = (r.w >= DROP_PROP) ? m.w * INV_KEEP : 0.0f;
    so.x = (r.x >= DROP_PROP) ? s.x * INV_D : 0.0f;
    so.y = (r.y >= DROP_PROP) ? s.y * INV_D : 0.0f;
    so.z = (r.z >= DROP_PROP) ? s.z * INV_D : 0.0f;
    so.w = (r.w >= DROP_PROP) ? s.w * INV_D : 0.0f;

    mu_out[i]    = mo;
    sigma_out[i] = so;
}

extern "C" void kernel_launch(void* const* d_in, const int* in_sizes, int n_in,
                              void* d_out, int out_size)
{
    const float* mu    = (const float*)d_in[0];
    const float* sigma = (const float*)d_in[1];
    const float* u     = (const float*)d_in[2];
    float* out = (float*)d_out;

    int n = in_sizes[0];            // 9,683,456 elements
    int n4 = n / 4;                 // 2,420,864 float4s

    float* mu_out    = out;         // outputs concatenated: (mu_out, Sigma_out)
    float* sigma_out = out + n;

    int threads = 256;
    int blocks = (n4 + threads - 1) / threads;   // 9457
    vdp_dropout_kernel<<<blocks, threads>>>(
        (const float4*)mu, (const float4*)sigma, (const float4*)u,
        (float4*)mu_out, (float4*)sigma_out, n4);
}

// round 15
// speedup vs baseline: 1.0302x; 1.0127x over previous
#include <cuda_runtime.h>
#include <cuda_bf16.h>
#include <cstdint>

// VDP dropout: keep = (u >= 0.1)
//   mu_out    = mu_in    * keep / 0.9
//   Sigma_out = Sigma_in * keep / 768
//
// FINAL — measured-best config across the full experiment matrix:
//   R1/R11-R14 (this config)          : 24.26-24.74us ncu  <= best
//   R3  VPT=4 front-batch + .cs both  : 25.86us (cross-CTA L1tex spread)
//   R4  .cs stores                    : 24.58us (neutral)
//   R6  persistent grid-stride        : 26.30us (fewer outstanding loads)
//   R10 512-thread blocks             : 25.54us (coarser sched granule)
// One float4 per thread, 256-thread blocks, one-shot grid (9457 CTAs),
// default cache policy. 193.7MB irreducible traffic (3R+2W, no reuse) at
// ~8.0 TB/s effective = ~100% of the HBM3e spec: streaming roofline.

static constexpr float DROP_PROP = 0.1f;
static constexpr float INV_KEEP  = 1.0f / (1.0f - DROP_PROP);   // 1/0.9
static constexpr float INV_D     = 1.0f / 768.0f;

__global__ void __launch_bounds__(256)
vdp_dropout_kernel(const float4* __restrict__ mu,
                   const float4* __restrict__ sigma,
                   const float4* __restrict__ u,
                   float4* __restrict__ mu_out,
                   float4* __restrict__ sigma_out,
                   int n4)
{
    int i = blockIdx.x * blockDim.x + threadIdx.x;
    if (i >= n4) return;

    float4 m = mu[i];
    float4 s = sigma[i];
    float4 r = u[i];

    float4 mo, so;
    mo.x = (r.x >= DROP_PROP) ? m.x * INV_KEEP : 0.0f;
    mo.y = (r.y >= DROP_PROP) ? m.y * INV_KEEP : 0.0f;
    mo.z = (r.z >= DROP_PROP) ? m.z * INV_KEEP : 0.0f;
    mo.w = (r.w >= DROP_PROP) ? m.w * INV_KEEP : 0.0f;
    so.x = (r.x >= DROP_PROP) ? s.x * INV_D : 0.0f;
    so.y = (r.y >= DROP_PROP) ? s.y * INV_D : 0.0f;
    so.z = (r.z >= DROP_PROP) ? s.z * INV_D : 0.0f;
    so.w = (r.w >= DROP_PROP) ? s.w * INV_D : 0.0f;

    mu_out[i]    = mo;
    sigma_out[i] = so;
}

extern "C" void kernel_launch(void* const* d_in, const int* in_sizes, int n_in,
                              void* d_out, int out_size)
{
    const float* mu    = (const float*)d_in[0];
    const float* sigma = (const float*)d_in[1];
    const float* u     = (const float*)d_in[2];
    float* out = (float*)d_out;

    int n = in_sizes[0];            // 9,683,456 elements
    int n4 = n / 4;                 // 2,420,864 float4s

    float* mu_out    = out;         // outputs concatenated: (mu_out, Sigma_out)
    float* sigma_out = out + n;

    int threads = 256;
    int blocks = (n4 + threads - 1) / threads;   // 9457
    vdp_dropout_kernel<<<blocks, threads>>>(
        (const float4*)mu, (const float4*)sigma, (const float4*)u,
        (float4*)mu_out, (float4*)sigma_out, n4);
}